// round 11
// baseline (speedup 1.0000x reference)
#include <cuda_runtime.h>

// MxCorrelation: out[b, (p+4)*9+(q+4), y, x] = (1/128) * sum_c a[b,c,y,x] * b[b,c,y+p,x+q]
// p,q in [-4,4], b zero-padded. in (8,128,128,128) f32, out (8,81,128,128) f32.
//
// R7: occupancy 3->4 blocks/SM (4 warps/SMSP) by shrinking the accumulator file.
//  - p-rows split 2+2+2+2+1 (grid.y=5): acc[2][9][4] = 72 regs, __launch_bounds__(128,4)
//  - group 4 (p0=+4) computes only pp=0 via a uniform branch
//  - scalar FFMA mainloop + cp.async double-buffered sB (R2 scheme, zero-once halo)
//  - static grid (persistent scheduling measured neutral in R6)

#define TY   4
#define CC   4
#define BR   5                 // TY + PGmax - 1 = 5 b-rows per p-group
#define BW   144               // 4 halo | 128 interior | 12 pad
#define NTHR 128
#define NCH  (128 / CC)
#define NSLOT 5                // CC*BR*32 float4 / 128 threads
#define SBHALF (CC * BR * BW * 4)   // 11520 bytes per buffer

__global__ __launch_bounds__(NTHR, 4)
void corr_kernel(const float* __restrict__ A, const float* __restrict__ Bm,
                 float* __restrict__ O) {
    __shared__ __align__(16) float sB[2][CC][BR][BW];   // 23 KB

    const int t  = threadIdx.x;
    const int xq = t & 31;
    const int yy = t >> 5;
    const int x0 = xq << 2;

    const int y0 = blockIdx.x * TY;
    const int pg = blockIdx.y;                // 0..4
    const int p0 = pg * 2 - 4;                // -4,-2,0,2,4
    const int PP = (pg == 4) ? 1 : 2;
    const int bb = blockIdx.z;

    const float* Ab = A  + (size_t)bb * 2097152;
    const float* Bb = Bm + (size_t)bb * 2097152;

    // zero both buffers once (halo + pad + invalid rows stay zero)
    float4* sB4 = (float4*)&sB[0][0][0][0];
#pragma unroll
    for (int i = 0; i < (2 * CC * BR * BW / 4 + NTHR - 1) / NTHR; i++) {
        int idx = t + i * NTHR;
        if (idx < 2 * CC * BR * BW / 4) sB4[idx] = make_float4(0.f, 0.f, 0.f, 0.f);
    }

    // fill descriptors: 5 interior float4 slots per thread
    const float* gptr[NSLOT];
    unsigned     sb0[NSLOT];
    bool         valid[NSLOT];
#pragma unroll
    for (int k = 0; k < NSLOT; k++) {
        int idx = k * NTHR + t;        // 0..639
        int col = idx & 31;
        int row = idx >> 5;            // 0..19
        int c   = row / BR;
        int r   = row - c * BR;
        int gy  = y0 + p0 + r;
        valid[k] = (unsigned)gy < 128u;
        gptr[k]  = Bb + (size_t)c * 16384 + gy * 128 + col * 4;
        sb0[k]   = (unsigned)__cvta_generic_to_shared(&sB[0][c][r][4 + col * 4]);
    }
    __syncthreads();   // zeros visible before cp.async lands

    // prologue fill: chunk 0 -> buffer 0
#pragma unroll
    for (int k = 0; k < NSLOT; k++) {
        if (valid[k])
            asm volatile("cp.async.cg.shared.global [%0], [%1], 16;\n"
                         :: "r"(sb0[k]), "l"(gptr[k]));
        gptr[k] += CC * 16384;
    }
    asm volatile("cp.async.commit_group;\n" ::: "memory");

    float acc[2][9][4];
#pragma unroll
    for (int pp = 0; pp < 2; pp++)
#pragma unroll
        for (int q = 0; q < 9; q++)
#pragma unroll
            for (int j = 0; j < 4; j++) acc[pp][q][j] = 0.0f;

    const float* Arow = Ab + (y0 + yy) * 128 + x0;

    for (int chunk = 0; chunk < NCH; chunk++) {
        const int buf  = chunk & 1;
        const int nbuf = buf ^ 1;

        float4 av[CC];
#pragma unroll
        for (int c = 0; c < CC; c++)
            av[c] = *(const float4*)(Arow + (size_t)(chunk * CC + c) * 16384);

        asm volatile("cp.async.wait_group 0;\n" ::: "memory");
        __syncthreads();

        if (chunk + 1 < NCH) {
#pragma unroll
            for (int k = 0; k < NSLOT; k++) {
                if (valid[k])
                    asm volatile("cp.async.cg.shared.global [%0], [%1], 16;\n"
                                 :: "r"(sb0[k] + nbuf * (unsigned)SBHALF), "l"(gptr[k]));
                gptr[k] += CC * 16384;
            }
        }
        asm volatile("cp.async.commit_group;\n" ::: "memory");

        // pp = 0 (always)
#pragma unroll
        for (int c = 0; c < CC; c++) {
            const float* row = &sB[buf][c][yy][0];
            float w[12];
            *(float4*)&w[0] = *(const float4*)&row[x0];
            *(float4*)&w[4] = *(const float4*)&row[x0 + 4];
            *(float4*)&w[8] = *(const float4*)&row[x0 + 8];
#pragma unroll
            for (int q = 0; q < 9; q++) {
                acc[0][q][0] += av[c].x * w[q];
                acc[0][q][1] += av[c].y * w[q + 1];
                acc[0][q][2] += av[c].z * w[q + 2];
                acc[0][q][3] += av[c].w * w[q + 3];
            }
        }
        // pp = 1 (uniform branch; skipped only by group 4)
        if (PP == 2) {
#pragma unroll
            for (int c = 0; c < CC; c++) {
                const float* row = &sB[buf][c][yy + 1][0];
                float w[12];
                *(float4*)&w[0] = *(const float4*)&row[x0];
                *(float4*)&w[4] = *(const float4*)&row[x0 + 4];
                *(float4*)&w[8] = *(const float4*)&row[x0 + 8];
#pragma unroll
                for (int q = 0; q < 9; q++) {
                    acc[1][q][0] += av[c].x * w[q];
                    acc[1][q][1] += av[c].y * w[q + 1];
                    acc[1][q][2] += av[c].z * w[q + 2];
                    acc[1][q][3] += av[c].w * w[q + 3];
                }
            }
        }
    }

    // epilogue: scale, float4 coalesced stores
    const float scale = 1.0f / 128.0f;
    float* Ob = O + (size_t)bb * 81 * 16384;
    for (int pp = 0; pp < PP; pp++) {
        int dbase = (p0 + pp + 4) * 9;
#pragma unroll
        for (int q = 0; q < 9; q++) {
            float4 v;
            v.x = acc[pp][q][0] * scale;
            v.y = acc[pp][q][1] * scale;
            v.z = acc[pp][q][2] * scale;
            v.w = acc[pp][q][3] * scale;
            *(float4*)&Ob[(size_t)(dbase + q) * 16384 + (y0 + yy) * 128 + x0] = v;
        }
    }
}

extern "C" void kernel_launch(void* const* d_in, const int* in_sizes, int n_in,
                              void* d_out, int out_size) {
    const float* A = (const float*)d_in[0];
    const float* B = (const float*)d_in[1];
    float*       O = (float*)d_out;

    dim3 grid(32, 5, 8);
    corr_kernel<<<grid, NTHR>>>(A, B, O);
}

// round 13
// speedup vs baseline: 1.1490x; 1.1490x over previous
#include <cuda_runtime.h>

// MxCorrelation: out[b, (p+4)*9+(q+4), y, x] = (1/128) * sum_c a[b,c,y,x] * b[b,c,y+p,x+q]
// p,q in [-4,4], b zero-padded. in (8,128,128,128) f32, out (8,81,128,128) f32.
//
// R12: barrier-free mainloop. Back to R2 shape (3 p-groups, occ 3, scalar FFMA),
// but sB is WARP-PRIVATE (each warp double-buffers its own 3 b-rows x CC channels),
// so the only sync is cp.async.wait_group on the warp's own fills. Zero
// __syncthreads => co-resident warps desynchronize, fma pipe never drains en masse.
//  - 12 cp.async per lane per chunk (3 rows x 4 ch interior), halo zeroed once
//  - A via direct prefetched LDG.128 (L2-resident)
//  - dynamic smem 52.2KB/block (4 warps x 2 buf x 4c x 3r x 136 floats)

#define TY    4
#define CC    4
#define ROWF  136                  // 4 halo | 128 interior | 4 pad (16B-aligned rows)
#define NTHR  128
#define NCH   32
#define PERBUF (CC * 3 * ROWF)     // floats per buffer per warp = 1632
#define WARPF  (2 * PERBUF)        // 3264 floats per warp
#define SMEMB  (4 * WARPF * 4)     // 52224 bytes per block

extern __shared__ float sW[];

__device__ __forceinline__ void fill_tile(unsigned sf, const float* gb,
                                          bool v0, bool v1, bool v2) {
#pragma unroll
    for (int c = 0; c < CC; c++) {
        if (v0) asm volatile("cp.async.cg.shared.global [%0], [%1], 16;\n"
                             :: "r"(sf + c * (3 * ROWF * 4)), "l"(gb + c * 16384));
        if (v1) asm volatile("cp.async.cg.shared.global [%0], [%1], 16;\n"
                             :: "r"(sf + c * (3 * ROWF * 4) + ROWF * 4), "l"(gb + c * 16384 + 128));
        if (v2) asm volatile("cp.async.cg.shared.global [%0], [%1], 16;\n"
                             :: "r"(sf + c * (3 * ROWF * 4) + 2 * ROWF * 4), "l"(gb + c * 16384 + 256));
    }
}

__global__ __launch_bounds__(NTHR, 3)
void corr_kernel(const float* __restrict__ A, const float* __restrict__ Bm,
                 float* __restrict__ O) {
    const int t    = threadIdx.x;
    const int lane = t & 31;
    const int wid  = t >> 5;          // warp id = yy (y row within tile)
    const int x0   = lane << 2;

    const int y0 = blockIdx.x * TY;
    const int p0 = (int)blockIdx.y * 3 - 4;
    const int bb = blockIdx.z;

    const float* Ab = A  + (size_t)bb * 2097152;
    const float* Bb = Bm + (size_t)bb * 2097152;

    float* wbase = sW + wid * WARPF;

    // zero this warp's region once (halo + invalid rows must stay 0)
    float4* z4 = (float4*)wbase;
#pragma unroll
    for (int i = 0; i < (WARPF / 4 + 31) / 32; i++) {
        int idx = lane + i * 32;
        if (idx < WARPF / 4) z4[idx] = make_float4(0.f, 0.f, 0.f, 0.f);
    }
    asm volatile("fence.proxy.async.shared::cta;" ::: "memory");  // zeros vs cp.async

    // warp-uniform row validity; per-lane fill addresses
    const int gy0 = y0 + p0 + wid;    // b-row for pp=0
    const bool v0 = (unsigned)(gy0)     < 128u;
    const bool v1 = (unsigned)(gy0 + 1) < 128u;
    const bool v2 = (unsigned)(gy0 + 2) < 128u;

    const float* gb = Bb + gy0 * 128 + lane * 4;   // never deref'd when invalid
    const unsigned sf =
        (unsigned)__cvta_generic_to_shared(wbase) + 16 + lane * 16;  // +16: skip halo

    // prologue: fill chunk 0 into buffer 0
    fill_tile(sf, gb, v0, v1, v2);
    gb += CC * 16384;
    asm volatile("cp.async.commit_group;\n" ::: "memory");

    float acc[3][9][4];
#pragma unroll
    for (int pp = 0; pp < 3; pp++)
#pragma unroll
        for (int q = 0; q < 9; q++)
#pragma unroll
            for (int j = 0; j < 4; j++) acc[pp][q][j] = 0.0f;

    const float* Arow = Ab + (y0 + wid) * 128 + x0;

    for (int chunk = 0; chunk < NCH; chunk++) {
        const int buf  = chunk & 1;
        const int nbuf = buf ^ 1;

        // prefetch A (independent of smem state)
        float4 av[CC];
#pragma unroll
        for (int c = 0; c < CC; c++)
            av[c] = *(const float4*)(Arow + (size_t)(chunk * CC + c) * 16384);

        // wait ONLY for this warp's previous fill; no block barrier anywhere
        asm volatile("cp.async.wait_group 0;\n" ::: "memory");

        // issue next fill into the other (already-consumed) buffer
        if (chunk + 1 < NCH) {
            fill_tile(sf + nbuf * (PERBUF * 4), gb, v0, v1, v2);
            gb += CC * 16384;
        }
        asm volatile("cp.async.commit_group;\n" ::: "memory");

        // compute: 4c x 3pp x (3 LDS.128 + 36 scalar FFMA)
        const float* base = wbase + buf * PERBUF;
#pragma unroll
        for (int c = 0; c < CC; c++) {
#pragma unroll
            for (int pp = 0; pp < 3; pp++) {
                const float* row = base + c * (3 * ROWF) + pp * ROWF;
                float w[12];
                *(float4*)&w[0] = *(const float4*)&row[x0];
                *(float4*)&w[4] = *(const float4*)&row[x0 + 4];
                *(float4*)&w[8] = *(const float4*)&row[x0 + 8];
#pragma unroll
                for (int q = 0; q < 9; q++) {
                    acc[pp][q][0] += av[c].x * w[q];
                    acc[pp][q][1] += av[c].y * w[q + 1];
                    acc[pp][q][2] += av[c].z * w[q + 2];
                    acc[pp][q][3] += av[c].w * w[q + 3];
                }
            }
        }
    }

    // epilogue: scale, float4 coalesced stores (acc in regs; no sync needed)
    const float scale = 1.0f / 128.0f;
    float* Ob = O + (size_t)bb * 81 * 16384;
#pragma unroll
    for (int pp = 0; pp < 3; pp++) {
        int dbase = (p0 + pp + 4) * 9;
#pragma unroll
        for (int q = 0; q < 9; q++) {
            float4 v;
            v.x = acc[pp][q][0] * scale;
            v.y = acc[pp][q][1] * scale;
            v.z = acc[pp][q][2] * scale;
            v.w = acc[pp][q][3] * scale;
            *(float4*)&Ob[(size_t)(dbase + q) * 16384 + (y0 + wid) * 128 + x0] = v;
        }
    }
}

extern "C" void kernel_launch(void* const* d_in, const int* in_sizes, int n_in,
                              void* d_out, int out_size) {
    const float* A = (const float*)d_in[0];
    const float* B = (const float*)d_in[1];
    float*       O = (float*)d_out;

    cudaFuncSetAttribute(corr_kernel, cudaFuncAttributeMaxDynamicSharedMemorySize, SMEMB);
    dim3 grid(32, 3, 8);
    corr_kernel<<<grid, NTHR, SMEMB>>>(A, B, O);
}